// round 16
// baseline (speedup 1.0000x reference)
#include <cuda_runtime.h>
#include <cuda_fp16.h>
#include <cstdint>

#define SEQ   2048
#define DIN   4096
#define NOUT  11008
#define KTOK  2201     // int(0.2 * 11008)
#define NCORE 4403     // int(0.4 * 11008)

#define TV_ELEMS ((size_t)SEQ * NOUT)
#define FW_ELEMS ((size_t)NCORE * DIN)

__device__ int g_counts[NOUT];
__device__ int g_core[NCORE];

// ---------------------------------------------------------------------------
// 1) GEMM + bias (fast path for output 0; selection boundaries re-verified
//    exactly later).  O[m][n] = f32( fp16(f32acc) + fp16(bias) )
// ---------------------------------------------------------------------------
#define BM 128
#define BN 128
#define BK 32
#define PAD 8

__device__ __forceinline__ void mma16816(
    float &d0, float &d1, float &d2, float &d3,
    uint32_t a0, uint32_t a1, uint32_t a2, uint32_t a3,
    uint32_t b0, uint32_t b1,
    float c0, float c1, float c2, float c3)
{
    asm volatile(
        "mma.sync.aligned.m16n8k16.row.col.f32.f16.f16.f32 "
        "{%0,%1,%2,%3},{%4,%5,%6,%7},{%8,%9},{%10,%11,%12,%13};\n"
        : "=f"(d0), "=f"(d1), "=f"(d2), "=f"(d3)
        : "r"(a0), "r"(a1), "r"(a2), "r"(a3), "r"(b0), "r"(b1),
          "f"(c0), "f"(c1), "f"(c2), "f"(c3));
}

__global__ __launch_bounds__(256, 2)
void gemm_bias_kernel(const float* __restrict__ X,
                      const float* __restrict__ W,
                      const float* __restrict__ Bias,
                      float* __restrict__ O)
{
    __shared__ __half As[BM][BK + PAD];
    __shared__ __half Bs[BN][BK + PAD];

    const int tid = threadIdx.x;
    const int bid = blockIdx.x;
    const int n0  = (bid >> 4) * BN;
    const int m0  = (bid & 15) * BM;
    const int warp = tid >> 5;
    const int lane = tid & 31;
    const int wm   = warp >> 2;
    const int wn   = warp & 3;
    const int g    = lane >> 2;
    const int tg   = lane & 3;

    float acc[4][4][4];
#pragma unroll
    for (int mi = 0; mi < 4; mi++)
#pragma unroll
        for (int ni = 0; ni < 4; ni++)
#pragma unroll
            for (int r = 0; r < 4; r++) acc[mi][ni][r] = 0.f;

    for (int k0 = 0; k0 < DIN; k0 += BK) {
#pragma unroll
        for (int s = 0; s < 4; s++) {
            int v  = tid + s * 256;
            int r  = v >> 3;
            int kc = (v & 7) * 4;
            float4 a = *(const float4*)&X[(size_t)(m0 + r) * DIN + k0 + kc];
            *(__half2*)&As[r][kc]     = __floats2half2_rn(a.x, a.y);
            *(__half2*)&As[r][kc + 2] = __floats2half2_rn(a.z, a.w);
            float4 b = *(const float4*)&W[(size_t)(n0 + r) * DIN + k0 + kc];
            *(__half2*)&Bs[r][kc]     = __floats2half2_rn(b.x, b.y);
            *(__half2*)&Bs[r][kc + 2] = __floats2half2_rn(b.z, b.w);
        }
        __syncthreads();

#pragma unroll
        for (int ks = 0; ks < 2; ks++) {
            const int c = ks * 16 + tg * 2;
            uint32_t af[4][4];
            uint32_t bf[4][2];
#pragma unroll
            for (int mi = 0; mi < 4; mi++) {
                int r = wm * 64 + mi * 16;
                af[mi][0] = *(const uint32_t*)&As[r + g][c];
                af[mi][1] = *(const uint32_t*)&As[r + g + 8][c];
                af[mi][2] = *(const uint32_t*)&As[r + g][c + 8];
                af[mi][3] = *(const uint32_t*)&As[r + g + 8][c + 8];
            }
#pragma unroll
            for (int ni = 0; ni < 4; ni++) {
                int n = wn * 32 + ni * 8 + g;
                bf[ni][0] = *(const uint32_t*)&Bs[n][c];
                bf[ni][1] = *(const uint32_t*)&Bs[n][c + 8];
            }
#pragma unroll
            for (int mi = 0; mi < 4; mi++)
#pragma unroll
                for (int ni = 0; ni < 4; ni++)
                    mma16816(acc[mi][ni][0], acc[mi][ni][1],
                             acc[mi][ni][2], acc[mi][ni][3],
                             af[mi][0], af[mi][1], af[mi][2], af[mi][3],
                             bf[ni][0], bf[ni][1],
                             acc[mi][ni][0], acc[mi][ni][1],
                             acc[mi][ni][2], acc[mi][ni][3]);
        }
        __syncthreads();
    }

#pragma unroll
    for (int mi = 0; mi < 4; mi++) {
#pragma unroll
        for (int ni = 0; ni < 4; ni++) {
            int row = m0 + wm * 64 + mi * 16 + g;
            int col = n0 + wn * 32 + ni * 8 + tg * 2;
            __half b0 = __float2half(Bias[col]);
            __half b1 = __float2half(Bias[col + 1]);
            __half h00 = __hadd(__float2half(acc[mi][ni][0]), b0);
            __half h01 = __hadd(__float2half(acc[mi][ni][1]), b1);
            __half h10 = __hadd(__float2half(acc[mi][ni][2]), b0);
            __half h11 = __hadd(__float2half(acc[mi][ni][3]), b1);
            float2 r0 = make_float2(__half2float(h00), __half2float(h01));
            float2 r1 = make_float2(__half2float(h10), __half2float(h11));
            *(float2*)&O[(size_t)row * NOUT + col] = r0;
            *(float2*)&O[(size_t)(row + 8) * NOUT + col] = r1;
        }
    }
}

// ---------------------------------------------------------------------------
// 2) Per-token top-KTOK, bit-exact vs XLA-CPU semantics:
//    fast radix select on approximate keys, then exact serial-f32-FMA
//    recomputation of the +/-3-key decision band.
// ---------------------------------------------------------------------------
__global__ void zero_counts_kernel()
{
    int i = blockIdx.x * blockDim.x + threadIdx.x;
    if (i < NOUT) g_counts[i] = 0;
}

__device__ __forceinline__ int f16key(__half h)
{
    unsigned short u = __half_as_ushort(h);
    unsigned short key = (u & 0x8000)
        ? (unsigned short)(~u)
        : (unsigned short)(u | 0x8000);
    return (int)key;
}

#define BANDCAP 512

__global__ __launch_bounds__(256)
void topk_count_kernel(const float* __restrict__ TV,
                       const float* __restrict__ X,
                       const float* __restrict__ W,
                       const float* __restrict__ Bias)
{
    __shared__ unsigned short skeys[NOUT];     // 22016 B
    __shared__ float          xrow[DIN];       // 16384 B
    __shared__ unsigned int   hist[256];
    __shared__ int            band_idx[BANDCAP];
    __shared__ int            band_key[BANDCAP];
    __shared__ int sh_b, sh_ghi, sh_T, sh_bandcnt, sh_nhi;

    const int tid = threadIdx.x;
    const int m   = blockIdx.x;
    const float* tv = TV + (size_t)m * NOUT;

    if (tid < 256) hist[tid] = 0u;
    if (tid == 0) { sh_bandcnt = 0; sh_nhi = 0; }
    __syncthreads();

    // Pass A: approximate keys + high-byte histogram
    for (int i = tid; i < NOUT; i += 256) {
        int key = f16key(__float2half(tv[i]));
        skeys[i] = (unsigned short)key;
        atomicAdd(&hist[key >> 8], 1u);
    }
    // x row into smem (for exact recompute)
    for (int k = tid; k < DIN; k += 256)
        xrow[k] = X[(size_t)m * DIN + k];
    __syncthreads();

    if (tid == 0) {
        unsigned cum = 0; int b = 0;
        for (int bin = 255; bin >= 0; --bin) {
            unsigned h = hist[bin];
            if (cum + h >= (unsigned)KTOK) { b = bin; break; }
            cum += h;
        }
        sh_b = b; sh_ghi = (int)cum;
    }
    __syncthreads();
    const int b = sh_b;
    const unsigned ghi = (unsigned)sh_ghi;

    if (tid < 256) hist[tid] = 0u;
    __syncthreads();

    for (int i = tid; i < NOUT; i += 256) {
        unsigned short key = skeys[i];
        if ((key >> 8) == b) atomicAdd(&hist[key & 0xFF], 1u);
    }
    __syncthreads();

    if (tid == 0) {
        unsigned r = (unsigned)KTOK - ghi;
        unsigned cum = 0; int l = 0;
        for (int bin = 255; bin >= 0; --bin) {
            unsigned h = hist[bin];
            if (cum + h >= r) { l = bin; break; }
            cum += h;
        }
        sh_T = (b << 8) | l;                   // KTOK-th largest approx key
    }
    __syncthreads();
    const int T = sh_T;

    // Pass C: certain winners (key > T+3) counted; band [T-3, T+3] collected.
    int my_hi = 0;
    for (int i = tid; i < NOUT; i += 256) {
        int key = (int)skeys[i];
        if (key > T + 3) {
            atomicAdd(&g_counts[i], 1);
            my_hi++;
        } else if (key >= T - 3) {
            int p = atomicAdd(&sh_bandcnt, 1);
            if (p < BANDCAP) band_idx[p] = i;
        }
    }
    atomicAdd(&sh_nhi, my_hi);
    __syncthreads();

    const int B = min(sh_bandcnt, BANDCAP);
    const int need = KTOK - sh_nhi;

    // Exact recompute of band entries: serial ascending-k f32 FMA
    // (replicates XLA-CPU / Eigen per-element accumulation), then
    // fp16 round + fp16 bias add — the reference's elementwise semantics.
    for (int s = tid; s < B; s += 256) {
        int n = band_idx[s];
        const float4* wr = (const float4*)(W + (size_t)n * DIN);
        float acc = 0.f;
#pragma unroll 4
        for (int kk = 0; kk < DIN / 4; kk++) {
            float4 w4 = __ldg(wr + kk);
            acc = fmaf(xrow[kk * 4 + 0], w4.x, acc);
            acc = fmaf(xrow[kk * 4 + 1], w4.y, acc);
            acc = fmaf(xrow[kk * 4 + 2], w4.z, acc);
            acc = fmaf(xrow[kk * 4 + 3], w4.w, acc);
        }
        __half h = __hadd(__float2half(acc), __float2half(Bias[n]));
        band_key[s] = f16key(h);
    }
    __syncthreads();

    // Band ranking: (exact key desc, index asc); select 'need' best.
    for (int s = tid; s < B; s += 256) {
        int ks = band_key[s], is = band_idx[s];
        int r = 0;
        for (int j = 0; j < B; j++) {
            int kj = band_key[j];
            if (kj > ks || (kj == ks && band_idx[j] < is)) r++;
        }
        if (r < need) atomicAdd(&g_counts[is], 1);
    }
}

// ---------------------------------------------------------------------------
// 3) Top-NCORE of counts (tie -> lower index), emitted sorted ascending.
//    Integer-exact, matches lax.top_k + sort.
// ---------------------------------------------------------------------------
__global__ void select_core_kernel()
{
    __shared__ unsigned int hist[SEQ + 1];
    __shared__ int s_gt[1024], s_eq[1024];
    __shared__ int sh_cstar, sh_t2;

    const int tid = threadIdx.x;               // 1024 threads

    for (int i = tid; i <= SEQ; i += 1024) hist[i] = 0u;
    __syncthreads();
    for (int i = tid; i < NOUT; i += 1024)
        atomicAdd(&hist[g_counts[i]], 1u);
    __syncthreads();

    if (tid == 0) {
        unsigned cum = 0; int cs = 0;
        for (int c = SEQ; c >= 0; --c) {
            unsigned h = hist[c];
            if (cum + h >= (unsigned)NCORE) { cs = c; break; }
            cum += h;
        }
        sh_cstar = cs;
        sh_t2 = NCORE - (int)cum;
    }
    __syncthreads();
    const int cstar = sh_cstar;
    const int t2 = sh_t2;

    const int CH = 11;
    const int base = tid * CH;
    int cloc[CH];
    int sgt = 0, seq_ = 0;
#pragma unroll
    for (int j = 0; j < CH; j++) {
        int i = base + j;
        int c = (i < NOUT) ? g_counts[i] : -1;
        cloc[j] = c;
        sgt  += (c > cstar);
        seq_ += (c == cstar);
    }
    s_gt[tid] = sgt; s_eq[tid] = seq_;
    __syncthreads();

    for (int off = 1; off < 1024; off <<= 1) {
        int vg = 0, ve = 0;
        if (tid >= off) { vg = s_gt[tid - off]; ve = s_eq[tid - off]; }
        __syncthreads();
        s_gt[tid] += vg; s_eq[tid] += ve;
        __syncthreads();
    }

    int gtb = s_gt[tid] - sgt;
    int eqb = s_eq[tid] - seq_;
#pragma unroll
    for (int j = 0; j < CH; j++) {
        int i = base + j;
        if (i >= NOUT) break;
        int c = cloc[j];
        if (c > cstar) {
            g_core[gtb + min(eqb, t2)] = i;
            gtb++;
        } else if (c == cstar) {
            if (eqb < t2) g_core[gtb + eqb] = i;
            eqb++;
        }
    }
}

// ---------------------------------------------------------------------------
// 4) Gather filtered_W rows + filtered_bias (bitwise copies of inputs).
// ---------------------------------------------------------------------------
__global__ void gather_kernel(const float* __restrict__ W,
                              const float* __restrict__ Bias,
                              float* __restrict__ O)
{
    const int j = blockIdx.x;
    const int idx = g_core[j];
    const float4* src = (const float4*)(W + (size_t)idx * DIN);
    float4* dst = (float4*)(O + TV_ELEMS + (size_t)j * DIN);
    for (int v = threadIdx.x; v < DIN / 4; v += blockDim.x)
        dst[v] = src[v];
    if (threadIdx.x == 0)
        O[TV_ELEMS + FW_ELEMS + j] = Bias[idx];
}

// ---------------------------------------------------------------------------
extern "C" void kernel_launch(void* const* d_in, const int* in_sizes, int n_in,
                              void* d_out, int out_size)
{
    const float* X    = (const float*)d_in[0];
    const float* W    = (const float*)d_in[1];
    const float* Bias = (const float*)d_in[2];
    float* O = (float*)d_out;

    gemm_bias_kernel<<<(NOUT / BN) * (SEQ / BM), 256>>>(X, W, Bias, O);
    zero_counts_kernel<<<(NOUT + 1023) / 1024, 1024>>>();
    topk_count_kernel<<<SEQ, 256>>>(O, X, W, Bias);
    select_core_kernel<<<1, 1024>>>();
    gather_kernel<<<NCORE, 256>>>(W, Bias, O);
}

// round 17
// speedup vs baseline: 1.0166x; 1.0166x over previous
#include <cuda_runtime.h>
#include <cuda_fp16.h>
#include <cstdint>

#define SEQ   2048
#define DIN   4096
#define NOUT  11008
#define KTOK  2201     // int(0.2 * 11008)
#define NCORE 4403     // int(0.4 * 11008)

#define TV_ELEMS ((size_t)SEQ * NOUT)
#define FW_ELEMS ((size_t)NCORE * DIN)

__device__ int g_counts[NOUT];
__device__ int g_core[NCORE];

// ---------------------------------------------------------------------------
// 1) GEMM + bias (fast path for output 0; selection boundaries re-verified
//    exactly later).  O[m][n] = f32( fp16(f32acc) + fp16(bias) )
// ---------------------------------------------------------------------------
#define BM 128
#define BN 128
#define BK 32
#define PAD 8

__device__ __forceinline__ void mma16816(
    float &d0, float &d1, float &d2, float &d3,
    uint32_t a0, uint32_t a1, uint32_t a2, uint32_t a3,
    uint32_t b0, uint32_t b1,
    float c0, float c1, float c2, float c3)
{
    asm volatile(
        "mma.sync.aligned.m16n8k16.row.col.f32.f16.f16.f32 "
        "{%0,%1,%2,%3},{%4,%5,%6,%7},{%8,%9},{%10,%11,%12,%13};\n"
        : "=f"(d0), "=f"(d1), "=f"(d2), "=f"(d3)
        : "r"(a0), "r"(a1), "r"(a2), "r"(a3), "r"(b0), "r"(b1),
          "f"(c0), "f"(c1), "f"(c2), "f"(c3));
}

__global__ __launch_bounds__(256, 2)
void gemm_bias_kernel(const float* __restrict__ X,
                      const float* __restrict__ W,
                      const float* __restrict__ Bias,
                      float* __restrict__ O)
{
    __shared__ __half As[BM][BK + PAD];
    __shared__ __half Bs[BN][BK + PAD];

    const int tid = threadIdx.x;
    const int bid = blockIdx.x;
    const int n0  = (bid >> 4) * BN;
    const int m0  = (bid & 15) * BM;
    const int warp = tid >> 5;
    const int lane = tid & 31;
    const int wm   = warp >> 2;
    const int wn   = warp & 3;
    const int g    = lane >> 2;
    const int tg   = lane & 3;

    float acc[4][4][4];
#pragma unroll
    for (int mi = 0; mi < 4; mi++)
#pragma unroll
        for (int ni = 0; ni < 4; ni++)
#pragma unroll
            for (int r = 0; r < 4; r++) acc[mi][ni][r] = 0.f;

    for (int k0 = 0; k0 < DIN; k0 += BK) {
#pragma unroll
        for (int s = 0; s < 4; s++) {
            int v  = tid + s * 256;
            int r  = v >> 3;
            int kc = (v & 7) * 4;
            float4 a = *(const float4*)&X[(size_t)(m0 + r) * DIN + k0 + kc];
            *(__half2*)&As[r][kc]     = __floats2half2_rn(a.x, a.y);
            *(__half2*)&As[r][kc + 2] = __floats2half2_rn(a.z, a.w);
            float4 b = *(const float4*)&W[(size_t)(n0 + r) * DIN + k0 + kc];
            *(__half2*)&Bs[r][kc]     = __floats2half2_rn(b.x, b.y);
            *(__half2*)&Bs[r][kc + 2] = __floats2half2_rn(b.z, b.w);
        }
        __syncthreads();

#pragma unroll
        for (int ks = 0; ks < 2; ks++) {
            const int c = ks * 16 + tg * 2;
            uint32_t af[4][4];
            uint32_t bf[4][2];
#pragma unroll
            for (int mi = 0; mi < 4; mi++) {
                int r = wm * 64 + mi * 16;
                af[mi][0] = *(const uint32_t*)&As[r + g][c];
                af[mi][1] = *(const uint32_t*)&As[r + g + 8][c];
                af[mi][2] = *(const uint32_t*)&As[r + g][c + 8];
                af[mi][3] = *(const uint32_t*)&As[r + g + 8][c + 8];
            }
#pragma unroll
            for (int ni = 0; ni < 4; ni++) {
                int n = wn * 32 + ni * 8 + g;
                bf[ni][0] = *(const uint32_t*)&Bs[n][c];
                bf[ni][1] = *(const uint32_t*)&Bs[n][c + 8];
            }
#pragma unroll
            for (int mi = 0; mi < 4; mi++)
#pragma unroll
                for (int ni = 0; ni < 4; ni++)
                    mma16816(acc[mi][ni][0], acc[mi][ni][1],
                             acc[mi][ni][2], acc[mi][ni][3],
                             af[mi][0], af[mi][1], af[mi][2], af[mi][3],
                             bf[ni][0], bf[ni][1],
                             acc[mi][ni][0], acc[mi][ni][1],
                             acc[mi][ni][2], acc[mi][ni][3]);
        }
        __syncthreads();
    }

#pragma unroll
    for (int mi = 0; mi < 4; mi++) {
#pragma unroll
        for (int ni = 0; ni < 4; ni++) {
            int row = m0 + wm * 64 + mi * 16 + g;
            int col = n0 + wn * 32 + ni * 8 + tg * 2;
            __half b0 = __float2half(Bias[col]);
            __half b1 = __float2half(Bias[col + 1]);
            __half h00 = __hadd(__float2half(acc[mi][ni][0]), b0);
            __half h01 = __hadd(__float2half(acc[mi][ni][1]), b1);
            __half h10 = __hadd(__float2half(acc[mi][ni][2]), b0);
            __half h11 = __hadd(__float2half(acc[mi][ni][3]), b1);
            float2 r0 = make_float2(__half2float(h00), __half2float(h01));
            float2 r1 = make_float2(__half2float(h10), __half2float(h11));
            *(float2*)&O[(size_t)row * NOUT + col] = r0;
            *(float2*)&O[(size_t)(row + 8) * NOUT + col] = r1;
        }
    }
}

// ---------------------------------------------------------------------------
// 2) Per-token top-KTOK, bit-exact vs XLA-CPU semantics:
//    fast radix select on approximate keys, then exact serial-f32-FMA
//    recomputation of the +/-3-key decision band.
// ---------------------------------------------------------------------------
__global__ void zero_counts_kernel()
{
    int i = blockIdx.x * blockDim.x + threadIdx.x;
    if (i < NOUT) g_counts[i] = 0;
}

__device__ __forceinline__ int f16key(__half h)
{
    unsigned short u = __half_as_ushort(h);
    unsigned short key = (u & 0x8000)
        ? (unsigned short)(~u)
        : (unsigned short)(u | 0x8000);
    return (int)key;
}

#define BANDCAP 512

__global__ __launch_bounds__(256)
void topk_count_kernel(const float* __restrict__ TV,
                       const float* __restrict__ X,
                       const float* __restrict__ W,
                       const float* __restrict__ Bias)
{
    __shared__ unsigned short skeys[NOUT];     // 22016 B
    __shared__ float          xrow[DIN];       // 16384 B
    __shared__ unsigned int   hist[256];
    __shared__ int            band_idx[BANDCAP];
    __shared__ int            band_key[BANDCAP];
    __shared__ int sh_b, sh_ghi, sh_T, sh_bandcnt, sh_nhi;

    const int tid = threadIdx.x;
    const int m   = blockIdx.x;
    const float* tv = TV + (size_t)m * NOUT;

    if (tid < 256) hist[tid] = 0u;
    if (tid == 0) { sh_bandcnt = 0; sh_nhi = 0; }
    __syncthreads();

    // Pass A: approximate keys + high-byte histogram
    for (int i = tid; i < NOUT; i += 256) {
        int key = f16key(__float2half(tv[i]));
        skeys[i] = (unsigned short)key;
        atomicAdd(&hist[key >> 8], 1u);
    }
    // x row into smem (for exact recompute)
    for (int k = tid; k < DIN; k += 256)
        xrow[k] = X[(size_t)m * DIN + k];
    __syncthreads();

    if (tid == 0) {
        unsigned cum = 0; int b = 0;
        for (int bin = 255; bin >= 0; --bin) {
            unsigned h = hist[bin];
            if (cum + h >= (unsigned)KTOK) { b = bin; break; }
            cum += h;
        }
        sh_b = b; sh_ghi = (int)cum;
    }
    __syncthreads();
    const int b = sh_b;
    const unsigned ghi = (unsigned)sh_ghi;

    if (tid < 256) hist[tid] = 0u;
    __syncthreads();

    for (int i = tid; i < NOUT; i += 256) {
        unsigned short key = skeys[i];
        if ((key >> 8) == b) atomicAdd(&hist[key & 0xFF], 1u);
    }
    __syncthreads();

    if (tid == 0) {
        unsigned r = (unsigned)KTOK - ghi;
        unsigned cum = 0; int l = 0;
        for (int bin = 255; bin >= 0; --bin) {
            unsigned h = hist[bin];
            if (cum + h >= r) { l = bin; break; }
            cum += h;
        }
        sh_T = (b << 8) | l;                   // KTOK-th largest approx key
    }
    __syncthreads();
    const int T = sh_T;

    // Pass C: certain winners (key > T+3) counted; band [T-3, T+3] collected.
    int my_hi = 0;
    for (int i = tid; i < NOUT; i += 256) {
        int key = (int)skeys[i];
        if (key > T + 3) {
            atomicAdd(&g_counts[i], 1);
            my_hi++;
        } else if (key >= T - 3) {
            int p = atomicAdd(&sh_bandcnt, 1);
            if (p < BANDCAP) band_idx[p] = i;
        }
    }
    atomicAdd(&sh_nhi, my_hi);
    __syncthreads();

    const int B = min(sh_bandcnt, BANDCAP);
    const int need = KTOK - sh_nhi;

    // Exact recompute of band entries: serial ascending-k f32 FMA
    // (replicates XLA-CPU / Eigen per-element accumulation), then
    // fp16 round + fp16 bias add — the reference's elementwise semantics.
    for (int s = tid; s < B; s += 256) {
        int n = band_idx[s];
        const float4* wr = (const float4*)(W + (size_t)n * DIN);
        float acc = 0.f;
#pragma unroll 4
        for (int kk = 0; kk < DIN / 4; kk++) {
            float4 w4 = __ldg(wr + kk);
            acc = fmaf(xrow[kk * 4 + 0], w4.x, acc);
            acc = fmaf(xrow[kk * 4 + 1], w4.y, acc);
            acc = fmaf(xrow[kk * 4 + 2], w4.z, acc);
            acc = fmaf(xrow[kk * 4 + 3], w4.w, acc);
        }
        __half h = __hadd(__float2half(acc), __float2half(Bias[n]));
        band_key[s] = f16key(h);
    }
    __syncthreads();

    // Band ranking: (exact key desc, index asc); select 'need' best.
    for (int s = tid; s < B; s += 256) {
        int ks = band_key[s], is = band_idx[s];
        int r = 0;
        for (int j = 0; j < B; j++) {
            int kj = band_key[j];
            if (kj > ks || (kj == ks && band_idx[j] < is)) r++;
        }
        if (r < need) atomicAdd(&g_counts[is], 1);
    }
}

// ---------------------------------------------------------------------------
// 3) Top-NCORE of counts (tie -> lower index), emitted sorted ascending.
//    Integer-exact, matches lax.top_k + sort.
// ---------------------------------------------------------------------------
__global__ void select_core_kernel()
{
    __shared__ unsigned int hist[SEQ + 1];
    __shared__ int s_gt[1024], s_eq[1024];
    __shared__ int sh_cstar, sh_t2;

    const int tid = threadIdx.x;               // 1024 threads

    for (int i = tid; i <= SEQ; i += 1024) hist[i] = 0u;
    __syncthreads();
    for (int i = tid; i < NOUT; i += 1024)
        atomicAdd(&hist[g_counts[i]], 1u);
    __syncthreads();

    if (tid == 0) {
        unsigned cum = 0; int cs = 0;
        for (int c = SEQ; c >= 0; --c) {
            unsigned h = hist[c];
            if (cum + h >= (unsigned)NCORE) { cs = c; break; }
            cum += h;
        }
        sh_cstar = cs;
        sh_t2 = NCORE - (int)cum;
    }
    __syncthreads();
    const int cstar = sh_cstar;
    const int t2 = sh_t2;

    const int CH = 11;
    const int base = tid * CH;
    int cloc[CH];
    int sgt = 0, seq_ = 0;
#pragma unroll
    for (int j = 0; j < CH; j++) {
        int i = base + j;
        int c = (i < NOUT) ? g_counts[i] : -1;
        cloc[j] = c;
        sgt  += (c > cstar);
        seq_ += (c == cstar);
    }
    s_gt[tid] = sgt; s_eq[tid] = seq_;
    __syncthreads();

    for (int off = 1; off < 1024; off <<= 1) {
        int vg = 0, ve = 0;
        if (tid >= off) { vg = s_gt[tid - off]; ve = s_eq[tid - off]; }
        __syncthreads();
        s_gt[tid] += vg; s_eq[tid] += ve;
        __syncthreads();
    }

    int gtb = s_gt[tid] - sgt;
    int eqb = s_eq[tid] - seq_;
#pragma unroll
    for (int j = 0; j < CH; j++) {
        int i = base + j;
        if (i >= NOUT) break;
        int c = cloc[j];
        if (c > cstar) {
            g_core[gtb + min(eqb, t2)] = i;
            gtb++;
        } else if (c == cstar) {
            if (eqb < t2) g_core[gtb + eqb] = i;
            eqb++;
        }
    }
}

// ---------------------------------------------------------------------------
// 4) Gather filtered_W rows + filtered_bias (bitwise copies of inputs).
// ---------------------------------------------------------------------------
__global__ void gather_kernel(const float* __restrict__ W,
                              const float* __restrict__ Bias,
                              float* __restrict__ O)
{
    const int j = blockIdx.x;
    const int idx = g_core[j];
    const float4* src = (const float4*)(W + (size_t)idx * DIN);
    float4* dst = (float4*)(O + TV_ELEMS + (size_t)j * DIN);
    for (int v = threadIdx.x; v < DIN / 4; v += blockDim.x)
        dst[v] = src[v];
    if (threadIdx.x == 0)
        O[TV_ELEMS + FW_ELEMS + j] = Bias[idx];
}

// ---------------------------------------------------------------------------
extern "C" void kernel_launch(void* const* d_in, const int* in_sizes, int n_in,
                              void* d_out, int out_size)
{
    const float* X    = (const float*)d_in[0];
    const float* W    = (const float*)d_in[1];
    const float* Bias = (const float*)d_in[2];
    float* O = (float*)d_out;

    gemm_bias_kernel<<<(NOUT / BN) * (SEQ / BM), 256>>>(X, W, Bias, O);
    zero_counts_kernel<<<(NOUT + 1023) / 1024, 1024>>>();
    topk_count_kernel<<<SEQ, 256>>>(O, X, W, Bias);
    select_core_kernel<<<1, 1024>>>();
    gather_kernel<<<NCORE, 256>>>(W, Bias, O);
}